// round 9
// baseline (speedup 1.0000x reference)
#include <cuda_runtime.h>

#define BSZ 8
#define SEQ 4096
#define NH 32
#define HD 128
#define QLR 1536
#define NQ (NH*HD)      // 4096
#define KVROW (NH*256)  // floats per (b,s) row = 8192
#define NCHUNK 4
#define CHUNK (SEQ/NCHUNK)   // 1024

#define RB 16            // r-split blocks for qproj
#define CB 32            // col blocks (128 cols each)
#define RPB (QLR/RB)     // 96 rows per block
#define RPW (RPB/8)      // 12 rows per warp

// Device-global scratch (no allocation allowed)
__device__ __align__(16) float g_qpart[RB * BSZ * NQ];        // 2 MB split-K partials
__device__ __align__(16) float g_po[BSZ * NH * NCHUNK * HD];  // unnormalized partial outputs
__device__ float g_pm[BSZ * NH * NCHUNK];                     // partial max
__device__ float g_ps[BSZ * NH * NCHUNK];                     // partial expsum
__device__ int   g_cnt[BSZ * NH];                             // combine tickets (reset each run)

// ---------------------------------------------------------------------------
// qproj stage 1: split-K partial GEMM. grid = CB*RB = 512 CTAs x 256 thr.
// Block = (128 cols, 96 rows). Warp streams 12 coalesced 512B row segments.
// ---------------------------------------------------------------------------
__global__ __launch_bounds__(256) void qproj1_kernel(const float* __restrict__ hs,
                                                     const float* __restrict__ W)
{
    __shared__ float4 part[8][32][BSZ];   // 32 KB

    const int cb   = blockIdx.x & (CB - 1);
    const int rb   = blockIdx.x >> 5;
    const int tid  = threadIdx.x;
    const int w    = tid >> 5;
    const int lane = tid & 31;

    const int n4 = cb * 128 + lane * 4;
    const int r0 = rb * RPB + w * RPW;

    float4 acc[BSZ];
#pragma unroll
    for (int b = 0; b < BSZ; ++b) acc[b] = make_float4(0.f, 0.f, 0.f, 0.f);

#pragma unroll
    for (int rr = 0; rr < RPW; ++rr) {
        const int r = r0 + rr;
        const float4 w4 = __ldcs((const float4*)(&W[(size_t)r * NQ + n4]));
#pragma unroll
        for (int b = 0; b < BSZ; ++b) {
            const float hb = __ldg(&hs[b * QLR + r]);
            acc[b].x += hb * w4.x;
            acc[b].y += hb * w4.y;
            acc[b].z += hb * w4.z;
            acc[b].w += hb * w4.w;
        }
    }

#pragma unroll
    for (int b = 0; b < BSZ; ++b) part[w][lane][b] = acc[b];
    __syncthreads();

    {
        const int b2 = tid >> 5;
        const int l2 = tid & 31;
        float4 s = part[0][l2][b2];
#pragma unroll
        for (int ww = 1; ww < 8; ++ww) {
            const float4 t = part[ww][l2][b2];
            s.x += t.x; s.y += t.y; s.z += t.z; s.w += t.w;
        }
        const int n = cb * 128 + l2 * 4;
        *(float4*)(&g_qpart[((size_t)rb * BSZ + b2) * NQ + n]) = s;
    }
}

// ---------------------------------------------------------------------------
// attention: split-KV with fused q-reduce prologue and fused combine epilogue.
// grid = BSZ*NH*NCHUNK = 1024 CTAs, 256 thr.
// ---------------------------------------------------------------------------
__global__ __launch_bounds__(256) void attn_kernel(const float* __restrict__ kv,
                                                   const float* __restrict__ bq,
                                                   float* __restrict__ out)
{
    __shared__ float  sc[CHUNK];          // 4 KB
    __shared__ float4 part[8][32];        // 4 KB
    __shared__ float  red[8];
    __shared__ float  qsm[HD];
    __shared__ int    ticket;

    const int id   = blockIdx.x;          // (b*NH + h)*NCHUNK + c
    const int c    = id & (NCHUNK - 1);
    const int bh   = id / NCHUNK;
    const int b    = bh >> 5;
    const int h    = bh & 31;
    const int tid  = threadIdx.x;
    const int w    = tid >> 5;
    const int lane = tid & 31;

    // ---------------- Prologue: reduce split-K q partials + bias ----------
    if (tid < 32) {
        const int n = h * HD + 4 * tid;
        float4 s = *(const float4*)(&bq[n]);
#pragma unroll
        for (int rb = 0; rb < RB; ++rb) {
            const float4 t = *(const float4*)(&g_qpart[((size_t)rb * BSZ + b) * NQ + n]);
            s.x += t.x; s.y += t.y; s.z += t.z; s.w += t.w;
        }
        *(float4*)(&qsm[4 * tid]) = s;
    }
    __syncthreads();

    const float4 qv = *(const float4*)(&qsm[4 * lane]);
    const float* kvb = kv + ((size_t)(b * SEQ + c * CHUNK) * NH + h) * 256;

    // ---------------- Pass 1: scores ----------------
#pragma unroll 2
    for (int i = 0; i < CHUNK / 32; ++i) {            // 32 iters, 4 s per warp
        float d0, d1, d2, d3;
        {
            const float4 k0 = __ldcs((const float4*)(kvb + (size_t)(w +  0 + 32*i) * KVROW + 4*lane));
            const float4 k1 = __ldcs((const float4*)(kvb + (size_t)(w +  8 + 32*i) * KVROW + 4*lane));
            const float4 k2 = __ldcs((const float4*)(kvb + (size_t)(w + 16 + 32*i) * KVROW + 4*lane));
            const float4 k3 = __ldcs((const float4*)(kvb + (size_t)(w + 24 + 32*i) * KVROW + 4*lane));
            d0 = k0.x*qv.x + k0.y*qv.y + k0.z*qv.z + k0.w*qv.w;
            d1 = k1.x*qv.x + k1.y*qv.y + k1.z*qv.z + k1.w*qv.w;
            d2 = k2.x*qv.x + k2.y*qv.y + k2.z*qv.z + k2.w*qv.w;
            d3 = k3.x*qv.x + k3.y*qv.y + k3.z*qv.z + k3.w*qv.w;
        }
        const float a0 = d0 + __shfl_xor_sync(0xffffffffu, d0, 16);
        const float a1 = d1 + __shfl_xor_sync(0xffffffffu, d1, 16);
        const float a2 = d2 + __shfl_xor_sync(0xffffffffu, d2, 16);
        const float a3 = d3 + __shfl_xor_sync(0xffffffffu, d3, 16);
        float m0 = (lane & 16) ? a1 : a0;
        float m1 = (lane & 16) ? a3 : a2;
        m0 += __shfl_xor_sync(0xffffffffu, m0, 8);
        m1 += __shfl_xor_sync(0xffffffffu, m1, 8);
        float n = (lane & 8) ? m1 : m0;
        n += __shfl_xor_sync(0xffffffffu, n, 4);
        n += __shfl_xor_sync(0xffffffffu, n, 2);
        n += __shfl_xor_sync(0xffffffffu, n, 1);
        if ((lane & 7) == 0) {
            const int j = ((lane >> 4) & 1) | (((lane >> 3) & 1) << 1);
            sc[w + 8 * j + 32 * i] = n;
        }
    }
    __syncthreads();

    // ---------------- Local softmax stats ----------------
    float m = -1e30f;
#pragma unroll
    for (int k = 0; k < CHUNK / 256; ++k)
        m = fmaxf(m, sc[tid + 256 * k]);
    m = fmaxf(m, __shfl_xor_sync(0xffffffffu, m, 16));
    m = fmaxf(m, __shfl_xor_sync(0xffffffffu, m, 8));
    m = fmaxf(m, __shfl_xor_sync(0xffffffffu, m, 4));
    m = fmaxf(m, __shfl_xor_sync(0xffffffffu, m, 2));
    m = fmaxf(m, __shfl_xor_sync(0xffffffffu, m, 1));
    if (lane == 0) red[w] = m;
    __syncthreads();

    float gmax = red[0];
#pragma unroll
    for (int ww = 1; ww < 8; ++ww) gmax = fmaxf(gmax, red[ww]);

    float lsum = 0.f;
#pragma unroll
    for (int k = 0; k < CHUNK / 256; ++k) {
        const float e = __expf(sc[tid + 256 * k] - gmax);
        sc[tid + 256 * k] = e;
        lsum += e;
    }
    lsum += __shfl_xor_sync(0xffffffffu, lsum, 16);
    lsum += __shfl_xor_sync(0xffffffffu, lsum, 8);
    lsum += __shfl_xor_sync(0xffffffffu, lsum, 4);
    lsum += __shfl_xor_sync(0xffffffffu, lsum, 2);
    lsum += __shfl_xor_sync(0xffffffffu, lsum, 1);
    __syncthreads();                  // done reading red (gmax)
    if (lane == 0) red[w] = lsum;
    __syncthreads();

    float total = red[0];
#pragma unroll
    for (int ww = 1; ww < 8; ++ww) total += red[ww];

    // ---------------- Pass 2: unnormalized output ----------------
    float4 acc0 = make_float4(0.f, 0.f, 0.f, 0.f);
    float4 acc1 = make_float4(0.f, 0.f, 0.f, 0.f);
    const float* vb = kvb + 128;
#pragma unroll 2
    for (int i = 0; i < CHUNK / 32; ++i) {
        {
            const int s = w + 32 * i;
            const float  p = sc[s];
            const float4 v = __ldcs((const float4*)(vb + (size_t)s * KVROW + 4 * lane));
            acc0.x += p * v.x; acc0.y += p * v.y; acc0.z += p * v.z; acc0.w += p * v.w;
        }
        {
            const int s = w + 8 + 32 * i;
            const float  p = sc[s];
            const float4 v = __ldcs((const float4*)(vb + (size_t)s * KVROW + 4 * lane));
            acc1.x += p * v.x; acc1.y += p * v.y; acc1.z += p * v.z; acc1.w += p * v.w;
        }
        {
            const int s = w + 16 + 32 * i;
            const float  p = sc[s];
            const float4 v = __ldcs((const float4*)(vb + (size_t)s * KVROW + 4 * lane));
            acc0.x += p * v.x; acc0.y += p * v.y; acc0.z += p * v.z; acc0.w += p * v.w;
        }
        {
            const int s = w + 24 + 32 * i;
            const float  p = sc[s];
            const float4 v = __ldcs((const float4*)(vb + (size_t)s * KVROW + 4 * lane));
            acc1.x += p * v.x; acc1.y += p * v.y; acc1.z += p * v.z; acc1.w += p * v.w;
        }
    }
    acc0.x += acc1.x; acc0.y += acc1.y; acc0.z += acc1.z; acc0.w += acc1.w;
    part[w][lane] = acc0;
    __syncthreads();

    if (tid < 32) {
        float4 r = part[0][tid];
#pragma unroll
        for (int ww = 1; ww < 8; ++ww) {
            const float4 t = part[ww][tid];
            r.x += t.x; r.y += t.y; r.z += t.z; r.w += t.w;
        }
        *(float4*)(&g_po[(size_t)id * HD + 4 * tid]) = r;   // unnormalized
        if (tid == 0) { g_pm[id] = gmax; g_ps[id] = total; }
    }

    // ---------------- Epilogue: last chunk CTA per (b,h) combines --------
    __threadfence();
    __syncthreads();
    if (tid == 0) ticket = atomicAdd(&g_cnt[bh], 1);
    __syncthreads();

    if (ticket == NCHUNK - 1) {
        if (tid == 0) g_cnt[bh] = 0;      // reset for graph replay
        __threadfence();                  // acquire: see other CTAs' partials
        if (tid < HD) {
            const int i0 = bh * NCHUNK;
            float gm = g_pm[i0];
#pragma unroll
            for (int cc = 1; cc < NCHUNK; ++cc) gm = fmaxf(gm, g_pm[i0 + cc]);
            float den = 0.f, num = 0.f;
#pragma unroll
            for (int cc = 0; cc < NCHUNK; ++cc) {
                const float e = __expf(g_pm[i0 + cc] - gm);
                den += e * g_ps[i0 + cc];
                num += e * g_po[(size_t)(i0 + cc) * HD + tid];
            }
            out[(size_t)bh * HD + tid] = num / den;
        }
    }
}

// ---------------------------------------------------------------------------
extern "C" void kernel_launch(void* const* d_in, const int* in_sizes, int n_in,
                              void* d_out, int out_size)
{
    const float* hs = (const float*)d_in[0];  // (8, 1536)
    const float* kv = (const float*)d_in[1];  // (8, 4096, 32, 256)
    const float* W  = (const float*)d_in[2];  // (1536, 4096)
    const float* bq = (const float*)d_in[3];  // (4096,)
    float* out = (float*)d_out;               // (8, 4096)

    qproj1_kernel<<<CB * RB, 256>>>(hs, W);
    attn_kernel<<<BSZ * NH * NCHUNK, 256>>>(kv, bq, out);
}

// round 11
// speedup vs baseline: 1.1032x; 1.1032x over previous
#include <cuda_runtime.h>

#define BSZ 8
#define SEQ 4096
#define NH 32
#define HD 128
#define QLR 1536
#define NQ (NH*HD)      // 4096
#define KVROW (NH*256)  // floats per (b,s) row = 8192
#define NCHUNK 8
#define CHUNK (SEQ/NCHUNK)   // 512

#define RB 16            // r-split blocks for qproj
#define CB 32            // col blocks (128 cols each)
#define RPB (QLR/RB)     // 96 rows per block
#define RPW (RPB/8)      // 12 rows per warp

// Device-global scratch (no allocation allowed)
__device__ __align__(16) float g_qpart[RB * BSZ * NQ];        // 2 MB split-K partials
__device__ __align__(16) float g_po[BSZ * NH * NCHUNK * HD];  // unnormalized partial outputs
__device__ float g_pm[BSZ * NH * NCHUNK];                     // partial max
__device__ float g_ps[BSZ * NH * NCHUNK];                     // partial expsum

// ---------------------------------------------------------------------------
// qproj stage 1: split-K partial GEMM. grid = CB*RB = 512 CTAs x 256 thr.
// Block = (128 cols, 96 rows). Warp streams 12 coalesced 512B row segments.
// ---------------------------------------------------------------------------
__global__ __launch_bounds__(256) void qproj1_kernel(const float* __restrict__ hs,
                                                     const float* __restrict__ W)
{
    __shared__ float4 part[8][32][BSZ];   // 32 KB

    const int cb   = blockIdx.x & (CB - 1);
    const int rb   = blockIdx.x >> 5;
    const int tid  = threadIdx.x;
    const int w    = tid >> 5;
    const int lane = tid & 31;

    const int n4 = cb * 128 + lane * 4;
    const int r0 = rb * RPB + w * RPW;

    float4 acc[BSZ];
#pragma unroll
    for (int b = 0; b < BSZ; ++b) acc[b] = make_float4(0.f, 0.f, 0.f, 0.f);

#pragma unroll
    for (int rr = 0; rr < RPW; ++rr) {
        const int r = r0 + rr;
        const float4 w4 = *(const float4*)(&W[(size_t)r * NQ + n4]);
#pragma unroll
        for (int b = 0; b < BSZ; ++b) {
            const float hb = __ldg(&hs[b * QLR + r]);
            acc[b].x += hb * w4.x;
            acc[b].y += hb * w4.y;
            acc[b].z += hb * w4.z;
            acc[b].w += hb * w4.w;
        }
    }

#pragma unroll
    for (int b = 0; b < BSZ; ++b) part[w][lane][b] = acc[b];
    __syncthreads();

    {
        const int b2 = tid >> 5;
        const int l2 = tid & 31;
        float4 s = part[0][l2][b2];
#pragma unroll
        for (int ww = 1; ww < 8; ++ww) {
            const float4 t = part[ww][l2][b2];
            s.x += t.x; s.y += t.y; s.z += t.z; s.w += t.w;
        }
        const int n = cb * 128 + l2 * 4;
        *(float4*)(&g_qpart[((size_t)rb * BSZ + b2) * NQ + n]) = s;
    }
}

// ---------------------------------------------------------------------------
// attention: split-KV with fused q-reduce prologue. grid = BSZ*NH*NCHUNK
// = 2048 CTAs, 256 thr. Plain cached loads (no .cs — measured regression).
// ---------------------------------------------------------------------------
__global__ __launch_bounds__(256) void attn_kernel(const float* __restrict__ kv,
                                                   const float* __restrict__ bq)
{
    __shared__ float  sc[CHUNK];          // 2 KB
    __shared__ float4 part[8][32];        // 4 KB
    __shared__ float  red[8];
    __shared__ float  qsm[HD];

    const int id   = blockIdx.x;          // (b*NH + h)*NCHUNK + c
    const int c    = id & (NCHUNK - 1);
    const int bh   = id / NCHUNK;
    const int b    = bh >> 5;
    const int h    = bh & 31;
    const int tid  = threadIdx.x;
    const int w    = tid >> 5;
    const int lane = tid & 31;

    // ---------------- Prologue: reduce split-K q partials + bias ----------
    if (tid < 32) {
        const int n = h * HD + 4 * tid;
        float4 s = *(const float4*)(&bq[n]);
#pragma unroll
        for (int rb = 0; rb < RB; ++rb) {
            const float4 t = *(const float4*)(&g_qpart[((size_t)rb * BSZ + b) * NQ + n]);
            s.x += t.x; s.y += t.y; s.z += t.z; s.w += t.w;
        }
        *(float4*)(&qsm[4 * tid]) = s;
    }
    __syncthreads();

    const float4 qv = *(const float4*)(&qsm[4 * lane]);
    const float* kvb = kv + ((size_t)(b * SEQ + c * CHUNK) * NH + h) * 256;

    // ---------------- Pass 1: scores ----------------
#pragma unroll 2
    for (int i = 0; i < CHUNK / 32; ++i) {            // 16 iters, 4 s per warp
        float d0, d1, d2, d3;
        {
            const float4 k0 = *(const float4*)(kvb + (size_t)(w +  0 + 32*i) * KVROW + 4*lane);
            const float4 k1 = *(const float4*)(kvb + (size_t)(w +  8 + 32*i) * KVROW + 4*lane);
            const float4 k2 = *(const float4*)(kvb + (size_t)(w + 16 + 32*i) * KVROW + 4*lane);
            const float4 k3 = *(const float4*)(kvb + (size_t)(w + 24 + 32*i) * KVROW + 4*lane);
            d0 = k0.x*qv.x + k0.y*qv.y + k0.z*qv.z + k0.w*qv.w;
            d1 = k1.x*qv.x + k1.y*qv.y + k1.z*qv.z + k1.w*qv.w;
            d2 = k2.x*qv.x + k2.y*qv.y + k2.z*qv.z + k2.w*qv.w;
            d3 = k3.x*qv.x + k3.y*qv.y + k3.z*qv.z + k3.w*qv.w;
        }
        const float a0 = d0 + __shfl_xor_sync(0xffffffffu, d0, 16);
        const float a1 = d1 + __shfl_xor_sync(0xffffffffu, d1, 16);
        const float a2 = d2 + __shfl_xor_sync(0xffffffffu, d2, 16);
        const float a3 = d3 + __shfl_xor_sync(0xffffffffu, d3, 16);
        float m0 = (lane & 16) ? a1 : a0;
        float m1 = (lane & 16) ? a3 : a2;
        m0 += __shfl_xor_sync(0xffffffffu, m0, 8);
        m1 += __shfl_xor_sync(0xffffffffu, m1, 8);
        float n = (lane & 8) ? m1 : m0;
        n += __shfl_xor_sync(0xffffffffu, n, 4);
        n += __shfl_xor_sync(0xffffffffu, n, 2);
        n += __shfl_xor_sync(0xffffffffu, n, 1);
        if ((lane & 7) == 0) {
            const int j = ((lane >> 4) & 1) | (((lane >> 3) & 1) << 1);
            sc[w + 8 * j + 32 * i] = n;
        }
    }
    __syncthreads();

    // ---------------- Local softmax stats ----------------
    float m = -1e30f;
#pragma unroll
    for (int k = 0; k < CHUNK / 256; ++k)
        m = fmaxf(m, sc[tid + 256 * k]);
    m = fmaxf(m, __shfl_xor_sync(0xffffffffu, m, 16));
    m = fmaxf(m, __shfl_xor_sync(0xffffffffu, m, 8));
    m = fmaxf(m, __shfl_xor_sync(0xffffffffu, m, 4));
    m = fmaxf(m, __shfl_xor_sync(0xffffffffu, m, 2));
    m = fmaxf(m, __shfl_xor_sync(0xffffffffu, m, 1));
    if (lane == 0) red[w] = m;
    __syncthreads();

    float gmax = red[0];
#pragma unroll
    for (int ww = 1; ww < 8; ++ww) gmax = fmaxf(gmax, red[ww]);

    float lsum = 0.f;
#pragma unroll
    for (int k = 0; k < CHUNK / 256; ++k) {
        const float e = __expf(sc[tid + 256 * k] - gmax);
        sc[tid + 256 * k] = e;
        lsum += e;
    }
    lsum += __shfl_xor_sync(0xffffffffu, lsum, 16);
    lsum += __shfl_xor_sync(0xffffffffu, lsum, 8);
    lsum += __shfl_xor_sync(0xffffffffu, lsum, 4);
    lsum += __shfl_xor_sync(0xffffffffu, lsum, 2);
    lsum += __shfl_xor_sync(0xffffffffu, lsum, 1);
    __syncthreads();                  // done reading red (gmax)
    if (lane == 0) red[w] = lsum;
    __syncthreads();

    float total = red[0];
#pragma unroll
    for (int ww = 1; ww < 8; ++ww) total += red[ww];

    // ---------------- Pass 2: unnormalized output ----------------
    float4 acc0 = make_float4(0.f, 0.f, 0.f, 0.f);
    float4 acc1 = make_float4(0.f, 0.f, 0.f, 0.f);
    const float* vb = kvb + 128;
#pragma unroll 2
    for (int i = 0; i < CHUNK / 32; ++i) {
        {
            const int s = w + 32 * i;
            const float  p = sc[s];
            const float4 v = *(const float4*)(vb + (size_t)s * KVROW + 4 * lane);
            acc0.x += p * v.x; acc0.y += p * v.y; acc0.z += p * v.z; acc0.w += p * v.w;
        }
        {
            const int s = w + 8 + 32 * i;
            const float  p = sc[s];
            const float4 v = *(const float4*)(vb + (size_t)s * KVROW + 4 * lane);
            acc1.x += p * v.x; acc1.y += p * v.y; acc1.z += p * v.z; acc1.w += p * v.w;
        }
        {
            const int s = w + 16 + 32 * i;
            const float  p = sc[s];
            const float4 v = *(const float4*)(vb + (size_t)s * KVROW + 4 * lane);
            acc0.x += p * v.x; acc0.y += p * v.y; acc0.z += p * v.z; acc0.w += p * v.w;
        }
        {
            const int s = w + 24 + 32 * i;
            const float  p = sc[s];
            const float4 v = *(const float4*)(vb + (size_t)s * KVROW + 4 * lane);
            acc1.x += p * v.x; acc1.y += p * v.y; acc1.z += p * v.z; acc1.w += p * v.w;
        }
    }
    acc0.x += acc1.x; acc0.y += acc1.y; acc0.z += acc1.z; acc0.w += acc1.w;
    part[w][lane] = acc0;
    __syncthreads();

    if (tid < 32) {
        float4 r = part[0][tid];
#pragma unroll
        for (int ww = 1; ww < 8; ++ww) {
            const float4 t = part[ww][tid];
            r.x += t.x; r.y += t.y; r.z += t.z; r.w += t.w;
        }
        *(float4*)(&g_po[(size_t)id * HD + 4 * tid]) = r;   // unnormalized
        if (tid == 0) { g_pm[id] = gmax; g_ps[id] = total; }
    }
}

// ---------------------------------------------------------------------------
// combine the NCHUNK partials. 256 blocks x 128 threads.
// ---------------------------------------------------------------------------
__global__ __launch_bounds__(128) void combine_kernel(float* __restrict__ out)
{
    const int bh = blockIdx.x;            // b*NH + h
    const int d  = threadIdx.x;
    const int i0 = bh * NCHUNK;

    float gm = g_pm[i0];
#pragma unroll
    for (int c = 1; c < NCHUNK; ++c) gm = fmaxf(gm, g_pm[i0 + c]);

    float den = 0.f, num = 0.f;
#pragma unroll
    for (int c = 0; c < NCHUNK; ++c) {
        const float e = __expf(g_pm[i0 + c] - gm);
        den += e * g_ps[i0 + c];
        num += e * g_po[(size_t)(i0 + c) * HD + d];
    }
    out[(size_t)bh * HD + d] = num / den;
}

// ---------------------------------------------------------------------------
extern "C" void kernel_launch(void* const* d_in, const int* in_sizes, int n_in,
                              void* d_out, int out_size)
{
    const float* hs = (const float*)d_in[0];  // (8, 1536)
    const float* kv = (const float*)d_in[1];  // (8, 4096, 32, 256)
    const float* W  = (const float*)d_in[2];  // (1536, 4096)
    const float* bq = (const float*)d_in[3];  // (4096,)
    float* out = (float*)d_out;               // (8, 4096)

    qproj1_kernel<<<CB * RB, 256>>>(hs, W);
    attn_kernel<<<BSZ * NH * NCHUNK, 256>>>(kv, bq);
    combine_kernel<<<BSZ * NH, 128>>>(out);
}